// round 8
// baseline (speedup 1.0000x reference)
#include <cuda_runtime.h>
#include <math.h>

// Problem constants (fixed benchmark shapes)
#define N_PTS   50000
#define C_FEAT  128
#define HF      480
#define WF      640
#define IMW     640
#define IMH     480
#define HW      (HF*WF)
#define NITERS  10

#define MTHREADS 256
#define NWARP    (MTHREADS/32)
#define MAXB     1184

// ---------------- persistent device state ----------------
// Packed pixel-major maps: per pixel 96 float4 = [fm(32 f4) | gx(32 f4) | gy(32 f4)]
__device__ float4 g_packed[(size_t)HW * 96];

__device__ double   g_part[29][MAXB];   // transposed: coalesced reads in block0 reduce
__device__ float    g_Rc[9], g_tc[3];   // candidate pose (block0 -> all blocks)
__device__ unsigned g_count = 0;        // barrier arrival counter (reset by releaser)
__device__ unsigned g_gen   = 0;        // barrier generation (monotonic, replay-safe)

// ---------------- transpose (C,H,W) x3 -> (pix, map, C) ----------------
__global__ __launch_bounds__(256) void transpose_kernel(
    const float* __restrict__ fm, const float* __restrict__ gx, const float* __restrict__ gy)
{
    __shared__ float sh[32][C_FEAT + 1];
    int b    = blockIdx.x;            // (HW/32)*3 blocks
    int map  = b / (HW / 32);
    int tile = b % (HW / 32);
    int pix0 = tile * 32;
    const float* src = (map == 0) ? fm : (map == 1) ? gx : gy;

    int t = threadIdx.x, lane = t & 31, grp = t >> 5;   // 8 groups
    #pragma unroll
    for (int cb = 0; cb < C_FEAT; cb += 8) {
        int ch = cb + grp;
        sh[lane][ch] = src[(size_t)ch * HW + pix0 + lane];
    }
    __syncthreads();
    float* out = (float*)g_packed;
    #pragma unroll
    for (int pb = 0; pb < 32; pb += 8) {
        int p = pb + grp;
        size_t base = (size_t)(pix0 + p) * 384 + (size_t)map * 128;
        #pragma unroll
        for (int k = 0; k < 4; k++)
            out[base + k * 32 + lane] = sh[p][k * 32 + lane];
    }
}

// ---------------- software grid barrier ----------------
__device__ __forceinline__ void gbar(int grid) {
    __syncthreads();
    if (threadIdx.x == 0) {
        unsigned gen = *(volatile unsigned*)&g_gen;
        __threadfence();
        unsigned old = atomicAdd(&g_count, 1u);
        if (old == (unsigned)grid - 1u) {
            g_count = 0;
            __threadfence();
            atomicAdd(&g_gen, 1u);
        } else {
            while (*(volatile unsigned*)&g_gen == gen) { }
        }
        __threadfence();
    }
    __syncthreads();
}

// ---------------- 6x6 LM solve + pose composition (block0 thread0 only) ----------------
__device__ __noinline__ void solve_compose(
    const double* __restrict__ GH, float lam_f, float lr_f,
    const float* __restrict__ Rcur, const float* __restrict__ tcur)
{
    double G[6];
    for (int j = 0; j < 6; j++) G[j] = GH[j];
    double H[6][6];
    {
        int idx = 6;
        for (int k = 0; k < 6; k++)
            for (int l = k; l < 6; l++) { H[k][l] = GH[idx]; H[l][k] = GH[idx]; idx++; }
    }
    double lam = (double)lam_f;
    for (int k = 0; k < 6; k++) H[k][k] += lam * (H[k][k] + 1e-9);

    double M[6][7];
    for (int k = 0; k < 6; k++) { for (int j = 0; j < 6; j++) M[k][j] = H[k][j]; M[k][6] = G[k]; }
    for (int k = 0; k < 6; k++) {
        int p = k; double mx = fabs(M[k][k]);
        for (int r = k + 1; r < 6; r++) if (fabs(M[r][k]) > mx) { mx = fabs(M[r][k]); p = r; }
        if (p != k) for (int j = k; j < 7; j++) { double tmp = M[k][j]; M[k][j] = M[p][j]; M[p][j] = tmp; }
        double inv = 1.0 / M[k][k];
        for (int j = k; j < 7; j++) M[k][j] *= inv;
        for (int r = 0; r < 6; r++) if (r != k) {
            double f = M[r][k];
            for (int j = k; j < 7; j++) M[r][j] -= f * M[k][j];
        }
    }
    double lr = (double)lr_f;
    double dt0 = -lr * M[0][6], dt1 = -lr * M[1][6], dt2 = -lr * M[2][6];
    double w0  = -lr * M[3][6], w1  = -lr * M[4][6], w2  = -lr * M[5][6];

    double th2 = w0*w0 + w1*w1 + w2*w2;
    double th  = sqrt(th2 + 1e-24);
    double a, b;
    if (th < 1e-4) { a = 1.0 - th2 / 6.0; b = 0.5 - th2 / 24.0; }
    else           { a = sin(th) / th;    b = (1.0 - cos(th)) / (th2 + 1e-24); }
    double W[9]  = {0, -w2, w1,  w2, 0, -w0,  -w1, w0, 0};
    double W2[9];
    for (int r = 0; r < 3; r++)
        for (int c = 0; c < 3; c++) {
            double s = 0;
            for (int k = 0; k < 3; k++) s += W[r*3+k] * W[k*3+c];
            W2[r*3+c] = s;
        }
    double dr[9];
    for (int i = 0; i < 9; i++) dr[i] = a * W[i] + b * W2[i];
    dr[0] += 1.0; dr[4] += 1.0; dr[8] += 1.0;

    double Rc[9], tc[3];
    for (int r = 0; r < 3; r++)
        for (int c = 0; c < 3; c++) {
            double s = 0;
            for (int k = 0; k < 3; k++) s += dr[r*3+k] * (double)Rcur[k*3+c];
            Rc[r*3+c] = s;
        }
    for (int r = 0; r < 3; r++) {
        double s = 0;
        for (int k = 0; k < 3; k++) s += dr[r*3+k] * (double)tcur[k];
        tc[r] = s;
    }
    tc[0] += dt0; tc[1] += dt1; tc[2] += dt2;

    for (int i = 0; i < 9; i++) g_Rc[i] = (float)Rc[i];
    for (int i = 0; i < 3; i++) g_tc[i] = (float)tc[i];
}

// ---------------- persistent mega-kernel ----------------
__global__ __launch_bounds__(MTHREADS, 3)
void mega_kernel(const float* __restrict__ pts, const float* __restrict__ fref,
                 const float* __restrict__ Kmat, const float* __restrict__ R0,
                 const float* __restrict__ t0, float* __restrict__ out, int grid)
{
    __shared__ int    s_pix[MTHREADS];
    __shared__ float  s_X[MTHREADS], s_Y[MTHREADS], s_Z[MTHREADS];
    __shared__ int    s_idx[MTHREADS];
    __shared__ int    s_wcnt[NWARP];
    __shared__ double sred[NWARP][29];
    __shared__ double red[29];
    __shared__ double sGH[27];
    __shared__ float  sRcur[9], stcur[3];
    __shared__ float  sstate[2];        // lam, lr
    __shared__ double sprev;

    const float fx = Kmat[0], cx = Kmat[2], fy = Kmat[4], cy = Kmat[5];
    const int lane = threadIdx.x & 31;
    const int wrp  = threadIdx.x >> 5;
    const float4* frf4 = (const float4*)fref;

    const int chunk = (N_PTS + grid - 1) / grid;
    const int base  = blockIdx.x * chunk;
    const int myn   = (base < N_PTS) ? min(chunk, N_PTS - base) : 0;

    for (int step = 0; step <= NITERS; step++) {
        const bool doGH = (step < NITERS);
        // ---- pose to evaluate ----
        float Rl[9], tl[3];
        if (step == 0) {
            #pragma unroll
            for (int i = 0; i < 9; i++) Rl[i] = R0[i];
            #pragma unroll
            for (int i = 0; i < 3; i++) tl[i] = t0[i];
        } else {
            #pragma unroll
            for (int i = 0; i < 9; i++) Rl[i] = g_Rc[i];
            #pragma unroll
            for (int i = 0; i < 3; i++) tl[i] = g_tc[i];
        }

        // per-lane f32 accumulators (no per-point cross-lane reduction!)
        float ga[6]  = {0,0,0,0,0,0};
        float ha[21] = {0,0,0,0,0,0,0,0,0,0,0,0,0,0,0,0,0,0,0,0,0};
        double acost = 0.0;
        int    validtot = 0;

        for (int tb = 0; tb < myn; tb += MTHREADS) {
            // ===== Phase A: thread-parallel projection + deterministic compaction =====
            int tloc = tb + threadIdx.x;
            bool valid = false;
            float X = 0.f, Y = 0.f, Z = 0.f;
            int pix = 0;
            if (tloc < myn) {
                int i = base + tloc;
                float X0 = pts[3*i], Y0 = pts[3*i+1], Z0 = pts[3*i+2];
                X = Rl[0]*X0 + Rl[1]*Y0 + Rl[2]*Z0 + tl[0];
                Y = Rl[3]*X0 + Rl[4]*Y0 + Rl[5]*Z0 + tl[1];
                Z = Rl[6]*X0 + Rl[7]*Y0 + Rl[8]*Z0 + tl[2];
                float u = (fx*X + cx*Z) / Z;
                float v = (fy*Y + cy*Z) / Z;
                u = fminf(fmaxf(u, -1e6f), 1e6f);
                v = fminf(fmaxf(v, -1e6f), 1e6f);
                int px = (int)rintf(u) - 1;
                int py = (int)rintf(v) - 1;
                valid = (px >= 0) && (py >= 0) && (px < IMW) && (py < IMH);
                pix = py * WF + px;
            }
            unsigned bal = __ballot_sync(0xffffffffu, valid);
            if (lane == 0) s_wcnt[wrp] = __popc(bal);
            __syncthreads();
            int off = 0, total = 0;
            #pragma unroll
            for (int w2 = 0; w2 < NWARP; w2++) {
                int c2 = s_wcnt[w2];
                if (w2 < wrp) off += c2;
                total += c2;
            }
            int pos = off + __popc(bal & ((1u << lane) - 1u));
            if (valid) {
                s_pix[pos] = pix; s_X[pos] = X; s_Y[pos] = Y; s_Z[pos] = Z;
                s_idx[pos] = base + tloc;
            }
            __syncthreads();
            validtot += total;

            // ===== Phase B: pure gather -> FMA stream, zero shuffles =====
            for (int j = wrp; j < total; j += NWARP) {
                const float4* pb = g_packed + (size_t)s_pix[j] * 96;
                float4 f  = pb[lane];
                float4 fr = frf4[(size_t)s_idx[j] * 32 + lane];

                float ex = f.x - fr.x, ey = f.y - fr.y, ez = f.z - fr.z, ew = f.w - fr.w;
                float e2 = ex*ex + ey*ey + ez*ez + ew*ew;
                acost += (double)e2;

                if (doGH) {
                    float4 a  = pb[32 + lane];
                    float4 bb = pb[64 + lane];
                    // per-lane partial dot products (4 channels each)
                    float sxe = a.x*ex + a.y*ey + a.z*ez + a.w*ew;
                    float sye = bb.x*ex + bb.y*ey + bb.z*ez + bb.w*ew;
                    float sxx = a.x*a.x + a.y*a.y + a.z*a.z + a.w*a.w;
                    float sxy = a.x*bb.x + a.y*bb.y + a.z*bb.z + a.w*bb.w;
                    float syy = bb.x*bb.x + bb.y*bb.y + bb.z*bb.z + bb.w*bb.w;

                    // warp-uniform A coefficients (every lane computes same values)
                    float Xp = s_X[j], Yp = s_Y[j], Zp = s_Z[j];
                    float Zs  = (fabsf(Zp) > 1e-6f) ? Zp : 1e-6f;
                    float iz  = 1.0f / Zs;
                    float iz2 = iz * iz;
                    // row0 (u): u1 = 0 ; row1 (v): v0 = 0
                    float u0 =  fx * iz;
                    float u2 = -fx * Xp * iz2;
                    float u3 = -fx * Xp * Yp * iz2;
                    float u4 =  fx * Zp * iz + fx * Xp * Xp * iz2;
                    float u5 = -fx * Yp * iz;
                    float v1 =  fy * iz;
                    float v2 = -fy * Yp * iz2;
                    float v3 = -fy * Zp * iz - fy * Yp * Yp * iz2;
                    float v4 =  fy * Xp * Yp * iz2;
                    float v5 =  fy * Xp * iz;

                    // gradient accumulation: g_j += sxe*u_j + sye*v_j
                    ga[0] += sxe * u0;
                    ga[1] += sye * v1;
                    ga[2] += sxe * u2 + sye * v2;
                    ga[3] += sxe * u3 + sye * v3;
                    ga[4] += sxe * u4 + sye * v4;
                    ga[5] += sxe * u5 + sye * v5;

                    // Cholesky of per-lane 2x2 Gram [[sxx,sxy],[sxy,syy]]:
                    // contribution = x x^T + y y^T with x = alpha*u + beta*v, y = gamma*v
                    float rs    = rsqrtf(sxx + 1e-30f);
                    float alpha = sxx * rs;
                    float beta  = sxy * rs;
                    float g2m   = fmaxf(syy - beta * beta, 0.0f);
                    float gamma = sqrtf(g2m);

                    float x0 = alpha * u0;
                    float x1 = beta  * v1;
                    float x2 = alpha * u2 + beta * v2;
                    float x3 = alpha * u3 + beta * v3;
                    float x4 = alpha * u4 + beta * v4;
                    float x5 = alpha * u5 + beta * v5;
                    float y1 = gamma * v1;
                    float y2 = gamma * v2;
                    float y3 = gamma * v3;
                    float y4 = gamma * v4;
                    float y5 = gamma * v5;

                    // upper-triangle Hessian accumulate (order (0,0),(0,1)..(5,5))
                    ha[0]  += x0*x0;
                    ha[1]  += x0*x1;
                    ha[2]  += x0*x2;
                    ha[3]  += x0*x3;
                    ha[4]  += x0*x4;
                    ha[5]  += x0*x5;
                    ha[6]  += x1*x1 + y1*y1;
                    ha[7]  += x1*x2 + y1*y2;
                    ha[8]  += x1*x3 + y1*y3;
                    ha[9]  += x1*x4 + y1*y4;
                    ha[10] += x1*x5 + y1*y5;
                    ha[11] += x2*x2 + y2*y2;
                    ha[12] += x2*x3 + y2*y3;
                    ha[13] += x2*x4 + y2*y4;
                    ha[14] += x2*x5 + y2*y5;
                    ha[15] += x3*x3 + y3*y3;
                    ha[16] += x3*x4 + y3*y4;
                    ha[17] += x3*x5 + y3*y5;
                    ha[18] += x4*x4 + y4*y4;
                    ha[19] += x4*x5 + y4*y5;
                    ha[20] += x5*x5 + y5*y5;
                }
            }
            __syncthreads();   // protect smem before next tile's Phase A
        }

        // ---- once-per-step cross-lane reduction (f32 butterflies) ----
        #pragma unroll
        for (int v = 0; v < 6; v++) {
            float s = ga[v];
            #pragma unroll
            for (int o = 16; o; o >>= 1) s += __shfl_xor_sync(0xffffffffu, s, o);
            if (lane == 0) sred[wrp][v] = (double)s;
        }
        #pragma unroll
        for (int v = 0; v < 21; v++) {
            float s = ha[v];
            #pragma unroll
            for (int o = 16; o; o >>= 1) s += __shfl_xor_sync(0xffffffffu, s, o);
            if (lane == 0) sred[wrp][6 + v] = (double)s;
        }
        {
            double s = acost;
            #pragma unroll
            for (int o = 16; o; o >>= 1) s += __shfl_xor_sync(0xffffffffu, s, o);
            if (lane == 0) sred[wrp][27] = s;
        }
        __syncthreads();
        if (threadIdx.x < 28) {
            double s = 0.0;
            #pragma unroll
            for (int jj = 0; jj < NWARP; jj++) s += sred[jj][threadIdx.x];
            g_part[threadIdx.x][blockIdx.x] = s;
        }
        if (threadIdx.x == 28) g_part[28][blockIdx.x] = (double)validtot;
        gbar(grid);

        // ---- block0: reduce partials (coalesced), accept, next candidate ----
        if (blockIdx.x == 0) {
            for (int vv = wrp; vv < 29; vv += NWARP) {
                double s = 0.0;
                for (int b2 = lane; b2 < grid; b2 += 32) s += g_part[vv][b2];
                #pragma unroll
                for (int o = 16; o; o >>= 1) s += __shfl_xor_sync(0xffffffffu, s, o);
                if (lane == 0) red[vv] = s;
            }
            __syncthreads();
            if (threadIdx.x == 0) {
                double cost = 0.5 * red[27] / fmax(red[28], 1.0);
                if (step == 0) {
                    sprev = cost;
                    for (int i = 0; i < 27; i++) sGH[i] = red[i];
                    for (int i = 0; i < 9; i++) sRcur[i] = R0[i];
                    for (int i = 0; i < 3; i++) stcur[i] = t0[i];
                    sstate[0] = 0.01f; sstate[1] = 1.0f;
                } else {
                    bool accept = (cost <= sprev);
                    float lam = sstate[0] * (accept ? 0.1f : 10.0f);
                    sstate[0] = fminf(fmaxf(lam, 1e-6f), 1e4f);
                    sstate[1] = accept ? 1.0f : fminf(fmaxf(0.1f * sstate[1], 1e-3f), 1.0f);
                    if (accept) {
                        for (int i = 0; i < 27; i++) sGH[i] = red[i];
                        for (int i = 0; i < 9; i++) sRcur[i] = g_Rc[i];
                        for (int i = 0; i < 3; i++) stcur[i] = g_tc[i];
                        sprev = cost;
                    }
                }
                if (step < NITERS) {
                    solve_compose(sGH, sstate[0], sstate[1], sRcur, stcur);
                } else {
                    for (int i = 0; i < 9; i++) out[i] = sRcur[i];
                    for (int i = 0; i < 3; i++) out[9 + i] = stcur[i];
                }
            }
        }
        gbar(grid);
    }
}

// ---------------- launch ----------------
extern "C" void kernel_launch(void* const* d_in, const int* in_sizes, int n_in,
                              void* d_out, int out_size)
{
    const float* pts  = (const float*)d_in[0];   // pts3D (N,3)
    const float* fref = (const float*)d_in[1];   // feature_ref (N,C)
    const float* fm   = (const float*)d_in[2];   // feature_map_query (C,H,W)
    const float* gx   = (const float*)d_in[3];   // feature_grad_x
    const float* gy   = (const float*)d_in[4];   // feature_grad_y
    const float* Km   = (const float*)d_in[5];   // K (3,3)
    const float* R0   = (const float*)d_in[6];   // R_init
    const float* t0   = (const float*)d_in[7];   // t_init

    transpose_kernel<<<(HW / 32) * 3, 256>>>(fm, gx, gy);

    // Size the persistent grid to guaranteed co-residency (deadlock-safe barrier).
    int dev = 0;
    cudaGetDevice(&dev);
    int nsm = 148;
    cudaDeviceGetAttribute(&nsm, cudaDevAttrMultiProcessorCount, dev);
    int maxb = 0;
    cudaOccupancyMaxActiveBlocksPerMultiprocessor(&maxb, mega_kernel, MTHREADS, 0);
    if (maxb < 1) maxb = 1;
    int grid = nsm * maxb;
    if (grid > MAXB) grid = MAXB;

    mega_kernel<<<grid, MTHREADS>>>(pts, fref, Km, R0, t0, (float*)d_out, grid);
}